// round 7
// baseline (speedup 1.0000x reference)
#include <cuda_runtime.h>
#include <cuda_fp16.h>

#define CANVAS 1024
#define NSH 64
#define TEXN 512
#define PT 528                   // padded row stride (texels), 128B-multiple (528*8B)
#define PH 514                   // padded rows: y = -1..512
#define PW 514                   // valid cols: x = -1..512 (cols 514..527 zero pad)
#define TEXSZ (PT * PH)          // entries per texture
#define T_EPS 1e-5f

// Interleaved fp16 RGBA texel = uint2 (rg, ba). Zero border rows/cols bake in
// the reference's out-of-bounds zero-fill: tap origin (xi,yi) in -1..512 maps
// to index (yi+1, xi+1) in 0..513 — always inside the padded array.
__device__ uint2 g_tex[4 * TEXSZ];   // ~8.7 MB scratch

// Per-shape transform/color record (compacted into smem per tile).
struct __align__(16) ShapeXfm {
    float tx, ty, m00, m01;
    float m10, m11, r, g;
    float b; int texoff; float pad0, pad1;
};

// ---------------------------------------------------------------------------
// Kernel 1: build padded interleaved fp16 texture.
// grid: (PH rows, 4 tex), block 256 sweeps PT cols.
// ---------------------------------------------------------------------------
__global__ __launch_bounds__(256) void build_tex_kernel(const float* __restrict__ tex) {
    int t = blockIdx.y;
    int row = blockIdx.x;              // 0..513
    int y = row - 1;                   // -1..512
    const int NPIX = TEXN * TEXN;
    const float* base = tex + (size_t)t * 4 * NPIX;
    uint2* orow = g_tex + t * TEXSZ + row * PT;

    bool yok = (unsigned)y < (unsigned)TEXN;
    for (int col = threadIdx.x; col < PT; col += 256) {
        int x = col - 1;
        bool ok = yok && ((unsigned)x < (unsigned)TEXN);
        float r = 0.f, g = 0.f, b = 0.f, a = 0.f;
        if (ok) {
            int off = y * TEXN + x;
            r = __ldg(base + off);
            g = __ldg(base + NPIX + off);
            b = __ldg(base + 2 * NPIX + off);
            a = __ldg(base + 3 * NPIX + off);
        }
        __half2 rg = __floats2half2_rn(r, g);
        __half2 ba = __floats2half2_rn(b, a);
        uint2 o;
        o.x = *reinterpret_cast<unsigned int*>(&rg);
        o.y = *reinterpret_cast<unsigned int*>(&ba);
        orow[col] = o;
    }
}

// ---------------------------------------------------------------------------
// Kernel 2: render. One thread per pixel. Per-tile shape compaction,
// reverse-order compositing with transmittance early-exit, fp16 4-tap bilerp.
// ---------------------------------------------------------------------------
__global__ __launch_bounds__(256) void render_kernel(const int* __restrict__ st,
                                                     const float* __restrict__ params,
                                                     float* __restrict__ out) {
    __shared__ ShapeXfm sxf[NSH];     // compacted, order-preserving
    __shared__ int s_cnt0;
    __shared__ int s_nlive;

    int tid = threadIdx.y * 32 + threadIdx.x;

    // tile bounds (pixel centers)
    float tX0 = (float)(blockIdx.x * 32) + 0.5f;
    float tX1 = tX0 + 31.0f;
    float tY0 = (float)(blockIdx.y * 8) + 0.5f;
    float tY1 = tY0 + 7.0f;

    // --- per-tile shape prep + compaction (first 2 warps) ---
    bool pass = false;
    ShapeXfm xf;
    if (tid < NSH) {
        const float* p = params + tid * 9;
        float tx = p[0] * (float)CANVAS;
        float ty = p[1] * (float)CANVAS;
        float W  = (float)CANVAS * (0.05f + 0.95f * p[2]);
        float H  = (float)CANVAS * (0.05f + 0.95f * p[3]);
        float as = p[4], ac = p[5];
        float nrm = sqrtf(as * as + ac * ac) + 1e-8f;
        float c = ac / nrm, s = as / nrm;
        float fx = (float)TEXN / W;
        float fy = (float)TEXN / H;

        xf.tx = tx; xf.ty = ty;
        xf.m00 =  c * fx;  xf.m01 = s * fx;
        xf.m10 = -s * fy;  xf.m11 = c * fy;
        xf.r = p[6]; xf.g = p[7]; xf.b = p[8];
        xf.texoff = st[tid] * TEXSZ;
        xf.pad0 = xf.pad1 = 0.f;

        float uh = 0.5f * W * (1.0f + 2.0f / TEXN) + 2.0f;
        float vh = 0.5f * H * (1.0f + 2.0f / TEXN) + 2.0f;
        float ex = fabsf(c) * uh + fabsf(s) * vh;
        float ey = fabsf(s) * uh + fabsf(c) * vh;
        pass = !(tX1 < tx - ex || tX0 > tx + ex || tY1 < ty - ey || tY0 > ty + ey);
    }

    unsigned mask = 0;
    int pos = 0;
    if (tid < NSH) {
        mask = __ballot_sync(0xffffffffu, pass);
        pos = __popc(mask & ((1u << (tid & 31)) - 1u));
        if (tid == 0) s_cnt0 = __popc(mask);
    }
    __syncthreads();
    if (tid < NSH) {
        int base = (tid < 32) ? 0 : s_cnt0;
        if (pass) sxf[base + pos] = xf;
        if (tid == 32) s_nlive = s_cnt0 + __popc(mask);
    }
    __syncthreads();

    int nlive = s_nlive;

    int x = blockIdx.x * 32 + threadIdx.x;
    int y = blockIdx.y * 8 + threadIdx.y;
    float px = (float)x + 0.5f;
    float py = (float)y + 0.5f;

    // Reverse compositing: out = C + T * canvas0(=1)
    float Cr = 0.0f, Cg = 0.0f, Cb = 0.0f;
    float T = 1.0f;

    for (int k = nlive - 1; k >= 0; k--) {
        if (__all_sync(0xffffffffu, T <= T_EPS)) break;
        if (T <= T_EPS) continue;

        const ShapeXfm rec = sxf[k];
        float dx = px - rec.tx;
        float dy = py - rec.ty;
        // fu = u + 1 (tap-origin index space), 255.5 + 1 folded into constant
        float fu = fmaf(rec.m00, dx, fmaf(rec.m01, dy, 256.5f));
        float fv = fmaf(rec.m10, dx, fmaf(rec.m11, dy, 256.5f));
        int xi1 = __float2int_rd(fu);   // 0..512 valid
        int yi1 = __float2int_rd(fv);
        if (((unsigned)xi1 > 512u) || ((unsigned)yi1 > 512u))
            continue;

        float wx = fu - (float)xi1;
        float wy = fv - (float)yi1;

        const uint2* t00 = g_tex + rec.texoff + yi1 * PT + xi1;
        uint2 q00 = __ldg(t00);
        uint2 q01 = __ldg(t00 + 1);
        uint2 q10 = __ldg(t00 + PT);
        uint2 q11 = __ldg(t00 + PT + 1);

        __half2 rg00 = *reinterpret_cast<const __half2*>(&q00.x);
        __half2 ba00 = *reinterpret_cast<const __half2*>(&q00.y);
        __half2 rg01 = *reinterpret_cast<const __half2*>(&q01.x);
        __half2 ba01 = *reinterpret_cast<const __half2*>(&q01.y);
        __half2 rg10 = *reinterpret_cast<const __half2*>(&q10.x);
        __half2 ba10 = *reinterpret_cast<const __half2*>(&q10.y);
        __half2 rg11 = *reinterpret_cast<const __half2*>(&q11.x);
        __half2 ba11 = *reinterpret_cast<const __half2*>(&q11.y);

        __half2 wx2 = __float2half2_rn(wx);
        __half2 wy2 = __float2half2_rn(wy);

        __half2 rg_t = __hfma2(wx2, __hsub2(rg01, rg00), rg00);
        __half2 ba_t = __hfma2(wx2, __hsub2(ba01, ba00), ba00);
        __half2 rg_b = __hfma2(wx2, __hsub2(rg11, rg10), rg10);
        __half2 ba_b = __hfma2(wx2, __hsub2(ba11, ba10), ba10);
        __half2 rg   = __hfma2(wy2, __hsub2(rg_b, rg_t), rg_t);
        __half2 ba   = __hfma2(wy2, __hsub2(ba_b, ba_t), ba_t);

        float2 rgf = __half22float2(rg);
        float2 baf = __half22float2(ba);

        float Ta = T * baf.y;           // T * alpha
        Cr = fmaf(Ta, rgf.x * rec.r, Cr);
        Cg = fmaf(Ta, rgf.y * rec.g, Cg);
        Cb = fmaf(Ta, baf.x * rec.b, Cb);
        T  = T - Ta;                    // T *= (1 - a)
    }

    int o = y * CANVAS + x;
    out[o] = Cr + T;
    out[CANVAS * CANVAS + o] = Cg + T;
    out[2 * CANVAS * CANVAS + o] = Cb + T;
}

// ---------------------------------------------------------------------------
extern "C" void kernel_launch(void* const* d_in, const int* in_sizes, int n_in,
                              void* d_out, int out_size) {
    const int*   shape_type = (const int*)d_in[0];
    const float* params     = (const float*)d_in[1];
    const float* textures   = (const float*)d_in[2];
    float* out = (float*)d_out;

    dim3 bgrid(PH, 4);
    build_tex_kernel<<<bgrid, 256>>>(textures);

    dim3 blk(32, 8);
    dim3 grd(CANVAS / 32, CANVAS / 8);
    render_kernel<<<grd, blk>>>(shape_type, params, out);
}

// round 8
// speedup vs baseline: 1.0684x; 1.0684x over previous
#include <cuda_runtime.h>
#include <cuda_fp16.h>

#define CANVAS 1024
#define NSH 64
#define TEXN 512
#define QDIM 513                 // tap-origin range (+1 offset): 0..512
#define QPAIR 257                // ceil(QDIM/2), 2x2 morton blocks per axis
#define QT (QPAIR * QPAIR * 4)   // entries per texture (swizzled, padded)
#define T_EPS 1e-4f

// One quad entry = the 2x2 bilinear tap block for tap-origin (yi, xi):
//   a: v00.rg, v00.ba, v01.rg, v01.ba   (fp16 pairs)
//   b: v10.rg, v10.ba, v11.rg, v11.ba
// Out-of-bounds taps stored as zero (matches reference zero-fill).
// Layout: 2x2 Morton blocks -> one 128B line = 2x2 neighborhood of tap origins.
struct __align__(32) Quad { uint4 a, b; };

__device__ Quad g_quad[4 * QT];   // ~33.8 MB scratch

__device__ __forceinline__ int quad_off(int qy, int qx) {
    return ((((qy >> 1) * QPAIR + (qx >> 1)) << 2) | ((qy & 1) << 1) | (qx & 1));
}

// Per-shape transform/color record (compacted into smem per tile).
struct __align__(16) ShapeXfm {
    float tx, ty, m00, m01;
    float m10, m11, r, g;
    float b; int texoff; float pad0, pad1;
};

// ---------------------------------------------------------------------------
// Kernel 1: build fp16 quad-gather table (Morton-swizzled).
// grid: (QDIM rows, 4 tex), block 256.
// ---------------------------------------------------------------------------
__global__ __launch_bounds__(256) void build_quad_kernel(const float* __restrict__ tex) {
    int t  = blockIdx.y;
    int qy = blockIdx.x;                   // 0..512
    int yi = qy - 1;                       // -1..511
    const int NPIX = TEXN * TEXN;
    const float* base = tex + (size_t)t * 4 * NPIX;
    Quad* qbase = g_quad + t * QT;

    for (int qx = threadIdx.x; qx < QDIM; qx += 256) {
        int xi = qx - 1;                   // -1..511

        float vals[4][4];  // [tap][chan]
        #pragma unroll
        for (int ty2 = 0; ty2 < 2; ty2++) {
            #pragma unroll
            for (int tx2 = 0; tx2 < 2; tx2++) {
                int y = yi + ty2, x = xi + tx2;
                bool ok = ((unsigned)x < (unsigned)TEXN) && ((unsigned)y < (unsigned)TEXN);
                int off = y * TEXN + x;
                #pragma unroll
                for (int ch = 0; ch < 4; ch++)
                    vals[ty2 * 2 + tx2][ch] = ok ? __ldg(base + ch * NPIX + off) : 0.0f;
            }
        }

        __half2 h[8];
        #pragma unroll
        for (int tap = 0; tap < 4; tap++) {
            h[tap * 2 + 0] = __floats2half2_rn(vals[tap][0], vals[tap][1]);
            h[tap * 2 + 1] = __floats2half2_rn(vals[tap][2], vals[tap][3]);
        }

        Quad q;
        q.a = *reinterpret_cast<uint4*>(&h[0]);
        q.b = *reinterpret_cast<uint4*>(&h[4]);
        qbase[quad_off(qy, qx)] = q;
    }
}

// ---------------------------------------------------------------------------
// Kernel 2: render. One thread per pixel; each WARP covers a compact 8x4
// pixel block (texture footprint ~8s x 4s instead of a 32s line segment ->
// fewer distinct 128B lines per LDG). Per-tile shape compaction, reverse
// compositing with transmittance early-exit, fp16 bilerp.
// ---------------------------------------------------------------------------
__global__ __launch_bounds__(256) void render_kernel(const int* __restrict__ st,
                                                     const float* __restrict__ params,
                                                     float* __restrict__ out) {
    __shared__ ShapeXfm sxf[NSH];     // compacted, order-preserving
    __shared__ int s_cnt0;
    __shared__ int s_nlive;

    int tid = threadIdx.x;            // 0..255 flat

    // tile bounds (pixel centers)
    float tX0 = (float)(blockIdx.x * 32) + 0.5f;
    float tX1 = tX0 + 31.0f;
    float tY0 = (float)(blockIdx.y * 8) + 0.5f;
    float tY1 = tY0 + 7.0f;

    // --- per-tile shape prep + compaction (first 2 warps) ---
    bool pass = false;
    ShapeXfm xf;
    if (tid < NSH) {
        const float* p = params + tid * 9;
        float tx = p[0] * (float)CANVAS;
        float ty = p[1] * (float)CANVAS;
        float W  = (float)CANVAS * (0.05f + 0.95f * p[2]);
        float H  = (float)CANVAS * (0.05f + 0.95f * p[3]);
        float as = p[4], ac = p[5];
        float nrm = sqrtf(as * as + ac * ac) + 1e-8f;
        float c = ac / nrm, s = as / nrm;
        float fx = (float)TEXN / W;
        float fy = (float)TEXN / H;

        xf.tx = tx; xf.ty = ty;
        xf.m00 =  c * fx;  xf.m01 = s * fx;
        xf.m10 = -s * fy;  xf.m11 = c * fy;
        xf.r = p[6]; xf.g = p[7]; xf.b = p[8];
        xf.texoff = st[tid] * QT;
        xf.pad0 = xf.pad1 = 0.f;

        float uh = 0.5f * W * (1.0f + 2.0f / TEXN) + 2.0f;
        float vh = 0.5f * H * (1.0f + 2.0f / TEXN) + 2.0f;
        float ex = fabsf(c) * uh + fabsf(s) * vh;
        float ey = fabsf(s) * uh + fabsf(c) * vh;
        pass = !(tX1 < tx - ex || tX0 > tx + ex || tY1 < ty - ey || tY0 > ty + ey);
    }

    unsigned mask = 0;
    int pos = 0;
    if (tid < NSH) {
        mask = __ballot_sync(0xffffffffu, pass);
        pos = __popc(mask & ((1u << (tid & 31)) - 1u));
        if (tid == 0) s_cnt0 = __popc(mask);
    }
    __syncthreads();
    if (tid < NSH) {
        int base = (tid < 32) ? 0 : s_cnt0;
        if (pass) sxf[base + pos] = xf;
        if (tid == 32) s_nlive = s_cnt0 + __popc(mask);
    }
    __syncthreads();

    int nlive = s_nlive;

    // warp -> 8x4 pixel block inside the 32x8 tile
    int lane = tid & 31;
    int warp = tid >> 5;              // 0..7
    int lx = lane & 7;                // 0..7
    int ly = lane >> 3;               // 0..3
    int x = blockIdx.x * 32 + (warp & 3) * 8 + lx;
    int y = blockIdx.y * 8 + (warp >> 2) * 4 + ly;
    float px = (float)x + 0.5f;
    float py = (float)y + 0.5f;

    // Reverse compositing: out = C + T * canvas0(=1)
    float Cr = 0.0f, Cg = 0.0f, Cb = 0.0f;
    float T = 1.0f;

    for (int k = nlive - 1; k >= 0; k--) {
        if (__all_sync(0xffffffffu, T <= T_EPS)) break;
        if (T <= T_EPS) continue;

        const ShapeXfm rec = sxf[k];
        float dx = px - rec.tx;
        float dy = py - rec.ty;
        // fu = u + 1 (tap-origin index space), 255.5 + 1 folded into constant
        float fu = fmaf(rec.m00, dx, fmaf(rec.m01, dy, 256.5f));
        float fv = fmaf(rec.m10, dx, fmaf(rec.m11, dy, 256.5f));
        int xi1 = __float2int_rd(fu);   // valid tap-origin index 0..512
        int yi1 = __float2int_rd(fv);
        if (((unsigned)xi1 >= (unsigned)QDIM) || ((unsigned)yi1 >= (unsigned)QDIM))
            continue;

        float wx = fu - (float)xi1;
        float wy = fv - (float)yi1;

        const uint4* q = reinterpret_cast<const uint4*>(
            g_quad + rec.texoff + quad_off(yi1, xi1));
        uint4 qa = __ldg(q);
        uint4 qb = __ldg(q + 1);

        __half2 rg00 = *reinterpret_cast<const __half2*>(&qa.x);
        __half2 ba00 = *reinterpret_cast<const __half2*>(&qa.y);
        __half2 rg01 = *reinterpret_cast<const __half2*>(&qa.z);
        __half2 ba01 = *reinterpret_cast<const __half2*>(&qa.w);
        __half2 rg10 = *reinterpret_cast<const __half2*>(&qb.x);
        __half2 ba10 = *reinterpret_cast<const __half2*>(&qb.y);
        __half2 rg11 = *reinterpret_cast<const __half2*>(&qb.z);
        __half2 ba11 = *reinterpret_cast<const __half2*>(&qb.w);

        __half2 wx2 = __float2half2_rn(wx);
        __half2 wy2 = __float2half2_rn(wy);

        __half2 rg_t = __hfma2(wx2, __hsub2(rg01, rg00), rg00);
        __half2 ba_t = __hfma2(wx2, __hsub2(ba01, ba00), ba00);
        __half2 rg_b = __hfma2(wx2, __hsub2(rg11, rg10), rg10);
        __half2 ba_b = __hfma2(wx2, __hsub2(ba11, ba10), ba10);
        __half2 rg   = __hfma2(wy2, __hsub2(rg_b, rg_t), rg_t);
        __half2 ba   = __hfma2(wy2, __hsub2(ba_b, ba_t), ba_t);

        float2 rgf = __half22float2(rg);
        float2 baf = __half22float2(ba);

        float Ta = T * baf.y;           // T * alpha
        Cr = fmaf(Ta, rgf.x * rec.r, Cr);
        Cg = fmaf(Ta, rgf.y * rec.g, Cg);
        Cb = fmaf(Ta, baf.x * rec.b, Cb);
        T  = T - Ta;                    // T *= (1 - a)
    }

    int o = y * CANVAS + x;
    out[o] = Cr + T;
    out[CANVAS * CANVAS + o] = Cg + T;
    out[2 * CANVAS * CANVAS + o] = Cb + T;
}

// ---------------------------------------------------------------------------
extern "C" void kernel_launch(void* const* d_in, const int* in_sizes, int n_in,
                              void* d_out, int out_size) {
    const int*   shape_type = (const int*)d_in[0];
    const float* params     = (const float*)d_in[1];
    const float* textures   = (const float*)d_in[2];
    float* out = (float*)d_out;

    dim3 bgrid(QDIM, 4);
    build_quad_kernel<<<bgrid, 256>>>(textures);

    dim3 blk(256);
    dim3 grd(CANVAS / 32, CANVAS / 8);
    render_kernel<<<grd, blk>>>(shape_type, params, out);
}

// round 9
// speedup vs baseline: 1.0940x; 1.0240x over previous
#include <cuda_runtime.h>
#include <cuda_fp16.h>

#define CANVAS 1024
#define NSH 64
#define TEXN 512
#define QDIM 513                 // tap-origin index range 0..512 (tex coord -1..511)
#define BW 129                   // morton blocks per row: ceil(513/4)
#define BH 257                   // morton block rows:     ceil(513/2)
#define QTE (BW * BH * 8)        // entries per table per texture
#define T_EPS 1e-4f

// Split quad storage: for tap-origin (yi, xi),
//   table A entry = { v00.rg, v00.ba, v01.rg, v01.ba }  (top row taps,    16B)
//   table B entry = { v10.rg, v10.ba, v11.rg, v11.ba }  (bottom row taps, 16B)
// Same index into both tables. 128B line = 8 origins (Morton 4 wide x 2 tall)
// -> ~2x origins per line vs the 32B fused quad => fewer distinct lines/LDG.
// Out-of-bounds taps stored as zero (matches reference zero-fill).
__device__ uint4 g_texA[4 * QTE];   // ~17 MB
__device__ uint4 g_texB[4 * QTE];   // ~17 MB

__device__ __forceinline__ int half_off(int qy, int qx) {
    return ((((qy >> 1) * BW + (qx >> 2)) << 3) | ((qy & 1) << 2) | (qx & 3));
}

// Per-shape transform/color record (compacted into smem per tile).
struct __align__(16) ShapeXfm {
    float tx, ty, m00, m01;
    float m10, m11, r, g;
    float b; int texoff; float pad0, pad1;
};

// ---------------------------------------------------------------------------
// Kernel 1: build the two fp16 half-tables (Morton 4x2 swizzled).
// grid: (QDIM rows, 4 tex), block 256.
// ---------------------------------------------------------------------------
__global__ __launch_bounds__(256) void build_quad_kernel(const float* __restrict__ tex) {
    int t  = blockIdx.y;
    int qy = blockIdx.x;                   // 0..512
    int yi = qy - 1;                       // -1..511
    const int NPIX = TEXN * TEXN;
    const float* base = tex + (size_t)t * 4 * NPIX;
    uint4* tabA = g_texA + t * QTE;
    uint4* tabB = g_texB + t * QTE;

    for (int qx = threadIdx.x; qx < QDIM; qx += 256) {
        int xi = qx - 1;                   // -1..511

        float vals[4][4];  // [tap][chan]  taps: 00,01,10,11
        #pragma unroll
        for (int ty2 = 0; ty2 < 2; ty2++) {
            #pragma unroll
            for (int tx2 = 0; tx2 < 2; tx2++) {
                int y = yi + ty2, x = xi + tx2;
                bool ok = ((unsigned)x < (unsigned)TEXN) && ((unsigned)y < (unsigned)TEXN);
                int off = y * TEXN + x;
                #pragma unroll
                for (int ch = 0; ch < 4; ch++)
                    vals[ty2 * 2 + tx2][ch] = ok ? __ldg(base + ch * NPIX + off) : 0.0f;
            }
        }

        __half2 h[8];
        #pragma unroll
        for (int tap = 0; tap < 4; tap++) {
            h[tap * 2 + 0] = __floats2half2_rn(vals[tap][0], vals[tap][1]);
            h[tap * 2 + 1] = __floats2half2_rn(vals[tap][2], vals[tap][3]);
        }

        int o = half_off(qy, qx);
        tabA[o] = *reinterpret_cast<uint4*>(&h[0]);   // v00, v01
        tabB[o] = *reinterpret_cast<uint4*>(&h[4]);   // v10, v11
    }
}

// ---------------------------------------------------------------------------
// Kernel 2: render. One thread per pixel; warp = compact 8x4 pixel block.
// Per-tile shape compaction + per-warp bbox cull, reverse compositing with
// transmittance early-exit, fp16 bilerp from split half-tables.
// ---------------------------------------------------------------------------
__global__ __launch_bounds__(256) void render_kernel(const int* __restrict__ st,
                                                     const float* __restrict__ params,
                                                     float* __restrict__ out) {
    __shared__ ShapeXfm sxf[NSH];     // compacted, order-preserving
    __shared__ float4   sbox[NSH];    // compacted bboxes (for warp-level cull)
    __shared__ int s_cnt0;
    __shared__ int s_nlive;

    int tid = threadIdx.x;            // 0..255 flat

    // tile bounds (pixel centers)
    float tX0 = (float)(blockIdx.x * 32) + 0.5f;
    float tX1 = tX0 + 31.0f;
    float tY0 = (float)(blockIdx.y * 8) + 0.5f;
    float tY1 = tY0 + 7.0f;

    // --- per-tile shape prep + compaction (first 2 warps) ---
    bool pass = false;
    ShapeXfm xf;
    float4 bbox;
    if (tid < NSH) {
        const float* p = params + tid * 9;
        float tx = p[0] * (float)CANVAS;
        float ty = p[1] * (float)CANVAS;
        float W  = (float)CANVAS * (0.05f + 0.95f * p[2]);
        float H  = (float)CANVAS * (0.05f + 0.95f * p[3]);
        float as = p[4], ac = p[5];
        float nrm = sqrtf(as * as + ac * ac) + 1e-8f;
        float c = ac / nrm, s = as / nrm;
        float fx = (float)TEXN / W;
        float fy = (float)TEXN / H;

        xf.tx = tx; xf.ty = ty;
        xf.m00 =  c * fx;  xf.m01 = s * fx;
        xf.m10 = -s * fy;  xf.m11 = c * fy;
        xf.r = p[6]; xf.g = p[7]; xf.b = p[8];
        xf.texoff = st[tid] * QTE;
        xf.pad0 = xf.pad1 = 0.f;

        float uh = 0.5f * W * (1.0f + 2.0f / TEXN) + 2.0f;
        float vh = 0.5f * H * (1.0f + 2.0f / TEXN) + 2.0f;
        float ex = fabsf(c) * uh + fabsf(s) * vh;
        float ey = fabsf(s) * uh + fabsf(c) * vh;
        bbox = make_float4(tx - ex, tx + ex, ty - ey, ty + ey);
        pass = !(tX1 < bbox.x || tX0 > bbox.y || tY1 < bbox.z || tY0 > bbox.w);
    }

    unsigned mask = 0;
    int pos = 0;
    if (tid < NSH) {
        mask = __ballot_sync(0xffffffffu, pass);
        pos = __popc(mask & ((1u << (tid & 31)) - 1u));
        if (tid == 0) s_cnt0 = __popc(mask);
    }
    __syncthreads();
    if (tid < NSH) {
        int base = (tid < 32) ? 0 : s_cnt0;
        if (pass) { sxf[base + pos] = xf; sbox[base + pos] = bbox; }
        if (tid == 32) s_nlive = s_cnt0 + __popc(mask);
    }
    __syncthreads();

    int nlive = s_nlive;

    // warp -> 8x4 pixel block inside the 32x8 tile
    int lane = tid & 31;
    int warp = tid >> 5;              // 0..7
    int lx = lane & 7;                // 0..7
    int ly = lane >> 3;               // 0..3
    int bx0 = blockIdx.x * 32 + (warp & 3) * 8;
    int by0 = blockIdx.y * 8 + (warp >> 2) * 4;
    int x = bx0 + lx;
    int y = by0 + ly;
    float px = (float)x + 0.5f;
    float py = (float)y + 0.5f;

    // warp block bounds (pixel centers) — warp-uniform
    float wX0 = (float)bx0 + 0.5f, wX1 = wX0 + 7.0f;
    float wY0 = (float)by0 + 0.5f, wY1 = wY0 + 3.0f;

    // Reverse compositing: out = C + T * canvas0(=1)
    float Cr = 0.0f, Cg = 0.0f, Cb = 0.0f;
    float T = 1.0f;

    for (int k = nlive - 1; k >= 0; k--) {
        if (__all_sync(0xffffffffu, T <= T_EPS)) break;

        // warp-uniform 8x4 bbox cull
        float4 bb = sbox[k];
        if (wX1 < bb.x || wX0 > bb.y || wY1 < bb.z || wY0 > bb.w)
            continue;
        if (T <= T_EPS) continue;

        const ShapeXfm rec = sxf[k];
        float dx = px - rec.tx;
        float dy = py - rec.ty;
        // fu = u + 1 (tap-origin index space), 255.5 + 1 folded into constant
        float fu = fmaf(rec.m00, dx, fmaf(rec.m01, dy, 256.5f));
        float fv = fmaf(rec.m10, dx, fmaf(rec.m11, dy, 256.5f));
        int xi1 = __float2int_rd(fu);   // valid tap-origin index 0..512
        int yi1 = __float2int_rd(fv);
        if (((unsigned)xi1 >= (unsigned)QDIM) || ((unsigned)yi1 >= (unsigned)QDIM))
            continue;

        float wx = fu - (float)xi1;
        float wy = fv - (float)yi1;

        int o = rec.texoff + half_off(yi1, xi1);
        uint4 qa = __ldg(g_texA + o);    // v00, v01
        uint4 qb = __ldg(g_texB + o);    // v10, v11

        __half2 rg00 = *reinterpret_cast<const __half2*>(&qa.x);
        __half2 ba00 = *reinterpret_cast<const __half2*>(&qa.y);
        __half2 rg01 = *reinterpret_cast<const __half2*>(&qa.z);
        __half2 ba01 = *reinterpret_cast<const __half2*>(&qa.w);
        __half2 rg10 = *reinterpret_cast<const __half2*>(&qb.x);
        __half2 ba10 = *reinterpret_cast<const __half2*>(&qb.y);
        __half2 rg11 = *reinterpret_cast<const __half2*>(&qb.z);
        __half2 ba11 = *reinterpret_cast<const __half2*>(&qb.w);

        __half2 wx2 = __float2half2_rn(wx);
        __half2 wy2 = __float2half2_rn(wy);

        __half2 rg_t = __hfma2(wx2, __hsub2(rg01, rg00), rg00);
        __half2 ba_t = __hfma2(wx2, __hsub2(ba01, ba00), ba00);
        __half2 rg_b = __hfma2(wx2, __hsub2(rg11, rg10), rg10);
        __half2 ba_b = __hfma2(wx2, __hsub2(ba11, ba10), ba10);
        __half2 rg   = __hfma2(wy2, __hsub2(rg_b, rg_t), rg_t);
        __half2 ba   = __hfma2(wy2, __hsub2(ba_b, ba_t), ba_t);

        float2 rgf = __half22float2(rg);
        float2 baf = __half22float2(ba);

        float Ta = T * baf.y;           // T * alpha
        Cr = fmaf(Ta, rgf.x * rec.r, Cr);
        Cg = fmaf(Ta, rgf.y * rec.g, Cg);
        Cb = fmaf(Ta, baf.x * rec.b, Cb);
        T  = T - Ta;                    // T *= (1 - a)
    }

    int o = y * CANVAS + x;
    out[o] = Cr + T;
    out[CANVAS * CANVAS + o] = Cg + T;
    out[2 * CANVAS * CANVAS + o] = Cb + T;
}

// ---------------------------------------------------------------------------
extern "C" void kernel_launch(void* const* d_in, const int* in_sizes, int n_in,
                              void* d_out, int out_size) {
    const int*   shape_type = (const int*)d_in[0];
    const float* params     = (const float*)d_in[1];
    const float* textures   = (const float*)d_in[2];
    float* out = (float*)d_out;

    dim3 bgrid(QDIM, 4);
    build_quad_kernel<<<bgrid, 256>>>(textures);

    dim3 blk(256);
    dim3 grd(CANVAS / 32, CANVAS / 8);
    render_kernel<<<grd, blk>>>(shape_type, params, out);
}

// round 10
// speedup vs baseline: 1.1391x; 1.0411x over previous
#include <cuda_runtime.h>
#include <cuda_fp16.h>

#define CANVAS 1024
#define NSH 64
#define TEXN 512
#define QDIM 513                 // tap-origin index range 0..512 (tex coord -1..511)
#define BW 129                   // morton blocks per row: ceil(513/4)
#define BH 257                   // morton block rows:     ceil(513/2)
#define QTE (BW * BH * 8)        // entries per table per texture
#define T_EPS 1e-4f

// Split quad storage: for tap-origin (yi, xi),
//   table A entry = { v00.rg, v00.ba, v01.rg, v01.ba }  (top row taps,    16B)
//   table B entry = { v10.rg, v10.ba, v11.rg, v11.ba }  (bottom row taps, 16B)
// Same index into both tables. 128B line = 8 origins (Morton 4 wide x 2 tall).
// Out-of-bounds taps stored as zero (matches reference zero-fill).
__device__ uint4 g_texA[4 * QTE];   // ~17 MB
__device__ uint4 g_texB[4 * QTE];   // ~17 MB

__device__ __forceinline__ int half_off(int qy, int qx) {
    return ((((qy >> 1) * BW + (qx >> 2)) << 3) | ((qy & 1) << 2) | (qx & 3));
}

// Per-shape transform/color record (compacted into smem per tile).
struct __align__(16) ShapeXfm {
    float tx, ty, m00, m01;
    float m10, m11, r, g;
    float b; int texoff; float pad0, pad1;
};

// ---------------------------------------------------------------------------
// Kernel 1: build the two fp16 half-tables (Morton 4x2 swizzled).
// ---------------------------------------------------------------------------
__global__ __launch_bounds__(256) void build_quad_kernel(const float* __restrict__ tex) {
    int t  = blockIdx.y;
    int qy = blockIdx.x;                   // 0..512
    int yi = qy - 1;                       // -1..511
    const int NPIX = TEXN * TEXN;
    const float* base = tex + (size_t)t * 4 * NPIX;
    uint4* tabA = g_texA + t * QTE;
    uint4* tabB = g_texB + t * QTE;

    for (int qx = threadIdx.x; qx < QDIM; qx += 256) {
        int xi = qx - 1;                   // -1..511

        float vals[4][4];  // [tap][chan]  taps: 00,01,10,11
        #pragma unroll
        for (int ty2 = 0; ty2 < 2; ty2++) {
            #pragma unroll
            for (int tx2 = 0; tx2 < 2; tx2++) {
                int y = yi + ty2, x = xi + tx2;
                bool ok = ((unsigned)x < (unsigned)TEXN) && ((unsigned)y < (unsigned)TEXN);
                int off = y * TEXN + x;
                #pragma unroll
                for (int ch = 0; ch < 4; ch++)
                    vals[ty2 * 2 + tx2][ch] = ok ? __ldg(base + ch * NPIX + off) : 0.0f;
            }
        }

        __half2 h[8];
        #pragma unroll
        for (int tap = 0; tap < 4; tap++) {
            h[tap * 2 + 0] = __floats2half2_rn(vals[tap][0], vals[tap][1]);
            h[tap * 2 + 1] = __floats2half2_rn(vals[tap][2], vals[tap][3]);
        }

        int o = half_off(qy, qx);
        tabA[o] = *reinterpret_cast<uint4*>(&h[0]);   // v00, v01
        tabB[o] = *reinterpret_cast<uint4*>(&h[4]);   // v10, v11
    }
}

// One bilinear sample + composite step. No-op if lane saturated or outside.
__device__ __forceinline__ void sample_composite(
    int texoff, float cr, float cg, float cb,
    float fu, float fv,
    float& Cr, float& Cg, float& Cb, float& T)
{
    if (T <= T_EPS) return;
    int xi1 = __float2int_rd(fu);
    int yi1 = __float2int_rd(fv);
    if (((unsigned)xi1 >= (unsigned)QDIM) || ((unsigned)yi1 >= (unsigned)QDIM))
        return;

    float wx = fu - (float)xi1;
    float wy = fv - (float)yi1;

    int o = texoff + half_off(yi1, xi1);
    uint4 qa = __ldg(g_texA + o);    // v00, v01
    uint4 qb = __ldg(g_texB + o);    // v10, v11

    __half2 rg00 = *reinterpret_cast<const __half2*>(&qa.x);
    __half2 ba00 = *reinterpret_cast<const __half2*>(&qa.y);
    __half2 rg01 = *reinterpret_cast<const __half2*>(&qa.z);
    __half2 ba01 = *reinterpret_cast<const __half2*>(&qa.w);
    __half2 rg10 = *reinterpret_cast<const __half2*>(&qb.x);
    __half2 ba10 = *reinterpret_cast<const __half2*>(&qb.y);
    __half2 rg11 = *reinterpret_cast<const __half2*>(&qb.z);
    __half2 ba11 = *reinterpret_cast<const __half2*>(&qb.w);

    __half2 wx2 = __float2half2_rn(wx);
    __half2 wy2 = __float2half2_rn(wy);

    __half2 rg_t = __hfma2(wx2, __hsub2(rg01, rg00), rg00);
    __half2 ba_t = __hfma2(wx2, __hsub2(ba01, ba00), ba00);
    __half2 rg_b = __hfma2(wx2, __hsub2(rg11, rg10), rg10);
    __half2 ba_b = __hfma2(wx2, __hsub2(ba11, ba10), ba10);
    __half2 rg   = __hfma2(wy2, __hsub2(rg_b, rg_t), rg_t);
    __half2 ba   = __hfma2(wy2, __hsub2(ba_b, ba_t), ba_t);

    float2 rgf = __half22float2(rg);
    float2 baf = __half22float2(ba);

    float Ta = T * baf.y;           // T * alpha
    Cr = fmaf(Ta, rgf.x * cr, Cr);
    Cg = fmaf(Ta, rgf.y * cg, Cg);
    Cb = fmaf(Ta, baf.x * cb, Cb);
    T  = T - Ta;                    // T *= (1 - a)
}

// ---------------------------------------------------------------------------
// Kernel 2: render. TWO pixels per thread (vertical pair); warp = 8x8 pixel
// block; block = 32x16 tile. Per-tile shape compaction + per-warp bbox cull,
// reverse compositing with transmittance early-exit, fp16 bilerp.
// ---------------------------------------------------------------------------
__global__ __launch_bounds__(256) void render_kernel(const int* __restrict__ st,
                                                     const float* __restrict__ params,
                                                     float* __restrict__ out) {
    __shared__ ShapeXfm sxf[NSH];     // compacted, order-preserving
    __shared__ float4   sbox[NSH];    // compacted bboxes (for warp-level cull)
    __shared__ int s_cnt0;
    __shared__ int s_nlive;

    int tid = threadIdx.x;            // 0..255 flat

    // tile bounds (pixel centers), tile = 32x16
    float tX0 = (float)(blockIdx.x * 32) + 0.5f;
    float tX1 = tX0 + 31.0f;
    float tY0 = (float)(blockIdx.y * 16) + 0.5f;
    float tY1 = tY0 + 15.0f;

    // --- per-tile shape prep + compaction (first 2 warps) ---
    bool pass = false;
    ShapeXfm xf;
    float4 bbox;
    if (tid < NSH) {
        const float* p = params + tid * 9;
        float tx = p[0] * (float)CANVAS;
        float ty = p[1] * (float)CANVAS;
        float W  = (float)CANVAS * (0.05f + 0.95f * p[2]);
        float H  = (float)CANVAS * (0.05f + 0.95f * p[3]);
        float as = p[4], ac = p[5];
        float nrm = sqrtf(as * as + ac * ac) + 1e-8f;
        float c = ac / nrm, s = as / nrm;
        float fx = (float)TEXN / W;
        float fy = (float)TEXN / H;

        xf.tx = tx; xf.ty = ty;
        xf.m00 =  c * fx;  xf.m01 = s * fx;
        xf.m10 = -s * fy;  xf.m11 = c * fy;
        xf.r = p[6]; xf.g = p[7]; xf.b = p[8];
        xf.texoff = st[tid] * QTE;
        xf.pad0 = xf.pad1 = 0.f;

        float uh = 0.5f * W * (1.0f + 2.0f / TEXN) + 2.0f;
        float vh = 0.5f * H * (1.0f + 2.0f / TEXN) + 2.0f;
        float ex = fabsf(c) * uh + fabsf(s) * vh;
        float ey = fabsf(s) * uh + fabsf(c) * vh;
        bbox = make_float4(tx - ex, tx + ex, ty - ey, ty + ey);
        pass = !(tX1 < bbox.x || tX0 > bbox.y || tY1 < bbox.z || tY0 > bbox.w);
    }

    unsigned mask = 0;
    int pos = 0;
    if (tid < NSH) {
        mask = __ballot_sync(0xffffffffu, pass);
        pos = __popc(mask & ((1u << (tid & 31)) - 1u));
        if (tid == 0) s_cnt0 = __popc(mask);
    }
    __syncthreads();
    if (tid < NSH) {
        int base = (tid < 32) ? 0 : s_cnt0;
        if (pass) { sxf[base + pos] = xf; sbox[base + pos] = bbox; }
        if (tid == 32) s_nlive = s_cnt0 + __popc(mask);
    }
    __syncthreads();

    int nlive = s_nlive;

    // warp -> 8x8 pixel block; thread -> vertical pixel pair
    int lane = tid & 31;
    int warp = tid >> 5;              // 0..7
    int lx = lane & 7;                // 0..7
    int lyt = lane >> 3;              // 0..3 -> rows 2*lyt, 2*lyt+1
    int bx0 = blockIdx.x * 32 + (warp & 3) * 8;
    int by0 = blockIdx.y * 16 + (warp >> 2) * 8;
    int x  = bx0 + lx;
    int y0 = by0 + lyt * 2;
    float px  = (float)x + 0.5f;
    float py0 = (float)y0 + 0.5f;

    // warp block bounds (pixel centers) — warp-uniform 8x8
    float wX0 = (float)bx0 + 0.5f, wX1 = wX0 + 7.0f;
    float wY0 = (float)by0 + 0.5f, wY1 = wY0 + 7.0f;

    // Reverse compositing per pixel: out = C + T * canvas0(=1)
    float Cr0 = 0.f, Cg0 = 0.f, Cb0 = 0.f, T0 = 1.f;
    float Cr1 = 0.f, Cg1 = 0.f, Cb1 = 0.f, T1 = 1.f;

    for (int k = nlive - 1; k >= 0; k--) {
        if (__all_sync(0xffffffffu, (T0 <= T_EPS) && (T1 <= T_EPS))) break;

        // warp-uniform 8x8 bbox cull
        float4 bb = sbox[k];
        if (wX1 < bb.x || wX0 > bb.y || wY1 < bb.z || wY0 > bb.w)
            continue;

        const ShapeXfm rec = sxf[k];
        float dx = px  - rec.tx;
        float dy = py0 - rec.ty;
        float fu0 = fmaf(rec.m00, dx, fmaf(rec.m01, dy, 256.5f));
        float fv0 = fmaf(rec.m10, dx, fmaf(rec.m11, dy, 256.5f));
        float fu1 = fu0 + rec.m01;     // +1 in canvas y
        float fv1 = fv0 + rec.m11;

        sample_composite(rec.texoff, rec.r, rec.g, rec.b, fu0, fv0, Cr0, Cg0, Cb0, T0);
        sample_composite(rec.texoff, rec.r, rec.g, rec.b, fu1, fv1, Cr1, Cg1, Cb1, T1);
    }

    int o = y0 * CANVAS + x;
    out[o] = Cr0 + T0;
    out[CANVAS * CANVAS + o] = Cg0 + T0;
    out[2 * CANVAS * CANVAS + o] = Cb0 + T0;
    o += CANVAS;
    out[o] = Cr1 + T1;
    out[CANVAS * CANVAS + o] = Cg1 + T1;
    out[2 * CANVAS * CANVAS + o] = Cb1 + T1;
}

// ---------------------------------------------------------------------------
extern "C" void kernel_launch(void* const* d_in, const int* in_sizes, int n_in,
                              void* d_out, int out_size) {
    const int*   shape_type = (const int*)d_in[0];
    const float* params     = (const float*)d_in[1];
    const float* textures   = (const float*)d_in[2];
    float* out = (float*)d_out;

    dim3 bgrid(QDIM, 4);
    build_quad_kernel<<<bgrid, 256>>>(textures);

    dim3 blk(256);
    dim3 grd(CANVAS / 32, CANVAS / 16);
    render_kernel<<<grd, blk>>>(shape_type, params, out);
}